// round 8
// baseline (speedup 1.0000x reference)
#include <cuda_runtime.h>

// Problem constants
#define N_PTS   16384
#define M_REF   4096
#define L_LAYERS 8
#define KMAX    7                    // Fourier order; trunc err ~ 6e-5 abs on e^{2cos}
#define RNK     (2*KMAX + 1)         // 15 features per coordinate
#define RPAD    16                   // padded row (float4-aligned)
#define R2      (RNK*RNK)            // 225
#define SPAD    (RNK*RPAD)           // 240
#define PBLK    64                   // producer blocks (S partials)
#define MPB     (M_REF / PBLK)       // 64 reference points per producer block
#define TPB     128
#define NBLK    (N_PTS / TPB)        // 128 consumer blocks
#define SCALE   4.4711032452e-6f     // exp(-4) / 4096

// Scratch (device global; fully rewritten by producer every call)
__device__ float g_SpartT[R2 * PBLK];   // transposed: [e][p], 256B rows

// c_0 = I_0(2), c_k = 2*I_k(2)
__constant__ float C_BES[KMAX + 1] = {
    2.27958530f, 3.18127371f, 1.37789690f, 0.42547992f,
    0.10145715f, 0.01965093f, 3.2003260e-3f, 4.4927600e-4f
};

__device__ __forceinline__ float ex2_approx(float d) {
    float r; asm("ex2.approx.ftz.f32 %0, %1;" : "=f"(r) : "f"(d)); return r;
}
__device__ __forceinline__ float rcp_approx(float d) {
    float r; asm("rcp.approx.ftz.f32 %0, %1;" : "=f"(r) : "f"(d)); return r;
}
// tanh via e^{2x}: 1 - 2/(e^{2x}+1). Saturates correctly. Rel err ~1e-6.
__device__ __forceinline__ float fast_tanh(float x) {
    float e = ex2_approx(x * 2.8853900817779268f);
    return fmaf(-2.0f, rcp_approx(e + 1.0f), 1.0f);
}

// Fourier features via MUFU sin/cos + Chebyshev recurrence.
template <bool WEIGHTED>
__device__ __forceinline__ void four_feats(float ang, float* out, float wscale) {
    float s = __sinf(ang);
    float c = __cosf(ang);
    float c2 = 2.0f * c;
    float ckm = 1.0f, skm = 0.0f;
    float ck  = c,    sk  = s;
    out[0] = WEIGHTED ? C_BES[0] * wscale : 1.0f;
    #pragma unroll
    for (int k = 1; k <= KMAX; k++) {
        float w = WEIGHTED ? C_BES[k] * wscale : 1.0f;
        out[k]        = w * ck;
        out[KMAX + k] = w * sk;
        float cn = fmaf(c2, ck, -ckm);
        float sn = fmaf(c2, sk, -skm);
        ckm = ck; skm = sk; ck = cn; sk = sn;
    }
}

// -------------------------------------------------------------------------
// Kernel 1 (primary): 64 producer blocks. Trigger PDL immediately so the
// consumer kernel launches and runs its independent prologue concurrently.
// Grid completion publishes g_SpartT (no fences/atomics needed).
// -------------------------------------------------------------------------
__global__ void __launch_bounds__(TPB) producer_kernel(
    const float* __restrict__ refset)
{
    cudaTriggerProgrammaticLaunchCompletion();

    __shared__ __align__(16) float V0[MPB * RNK];
    __shared__ __align__(16) float V1[MPB * RNK];

    const int b   = blockIdx.x;
    const int tid = threadIdx.x;

    if (tid < MPB) {
        int m = b * MPB + tid;
        float2 g = ((const float2*)refset)[m];
        float v0[RNK], v1[RNK];
        four_feats<true>(g.x, v0, SCALE);   // e^-4/M folded into v0
        four_feats<true>(g.y, v1, 1.0f);
        #pragma unroll
        for (int i = 0; i < RNK; i++) {
            V0[tid * RNK + i] = v0[i];
            V1[tid * RNK + i] = v1[i];
        }
    }
    __syncthreads();

    int e0 = tid;              // < 128 (R2 = 225)
    int e1 = tid + TPB;        // valid if < 225
    int j0 = e0 / RNK, k0 = e0 - j0 * RNK;
    int j1 = e1 / RNK, k1 = e1 - j1 * RNK;
    bool has1 = (e1 < R2);

    float a0 = 0.f, a1 = 0.f, c0 = 0.f, c1 = 0.f;
    #pragma unroll 8
    for (int mm = 0; mm < MPB; mm += 2) {
        a0 = fmaf(V0[(mm + 0) * RNK + j0], V1[(mm + 0) * RNK + k0], a0);
        a1 = fmaf(V0[(mm + 1) * RNK + j0], V1[(mm + 1) * RNK + k0], a1);
        if (has1) {
            c0 = fmaf(V0[(mm + 0) * RNK + j1], V1[(mm + 0) * RNK + k1], c0);
            c1 = fmaf(V0[(mm + 1) * RNK + j1], V1[(mm + 1) * RNK + k1], c1);
        }
    }
    g_SpartT[e0 * PBLK + b] = a0 + a1;
    if (has1) g_SpartT[e1 * PBLK + b] = c0 + c1;
}

// -------------------------------------------------------------------------
// Kernel 2 (secondary, PDL): launches while kernel 1 runs. Independent
// prologue (tanh chain + u-features) overlaps the producer; then a hardware
// grid-dependency sync, S reduction, bilinear form, MLP, softmax.
// -------------------------------------------------------------------------
__global__ void __launch_bounds__(TPB) consumer_kernel(
    const float* __restrict__ x,
    const float* __restrict__ layer_W,
    const float* __restrict__ layer_b,
    const float* __restrict__ layer_scale,
    const float* __restrict__ layer_shift,
    const float* __restrict__ W1,
    const float* __restrict__ b1,
    const float* __restrict__ W2,
    const float* __restrict__ b2,
    float* __restrict__ out)
{
    __shared__ __align__(16) float S[SPAD];   // 15 x 16 padded (960 B)

    const int tid = threadIdx.x;
    const int n   = blockIdx.x * TPB + tid;

    // ---------- independent prologue (overlaps producer kernel) ----------
    float2 xin = ((const float2*)x)[n];
    float h0 = xin.x, h1 = xin.y;
    #pragma unroll
    for (int l = 0; l < L_LAYERS; l++) {
        float w00 = layer_W[l * 4 + 0], w01 = layer_W[l * 4 + 1];
        float w10 = layer_W[l * 4 + 2], w11 = layer_W[l * 4 + 3];
        float c0  = layer_b[l * 2 + 0],  c1  = layer_b[l * 2 + 1];
        float sc0 = layer_scale[l * 2 + 0], sc1 = layer_scale[l * 2 + 1];
        float t0  = layer_shift[l * 2 + 0], t1  = layer_shift[l * 2 + 1];
        float u0 = fast_tanh(fmaf(h0, w00, fmaf(h1, w01, c0)));
        float u1 = fast_tanh(fmaf(h0, w10, fmaf(h1, w11, c1)));
        h0 = fmaf(u0, sc0, t0);
        h1 = fmaf(u1, sc1, t1);
    }

    float u0[RNK];
    __align__(16) float u1[RPAD];
    four_feats<false>(h0, u0, 1.0f);
    four_feats<false>(h1, u1, 1.0f);
    u1[RPAD - 1] = 0.0f;

    // ---------- wait for producer grid (memory-visible) ----------
    cudaGridDependencySynchronize();

    // ---------- reduce 64 transposed partials (16 coalesced float4) -------
    #pragma unroll
    for (int pass = 0; pass < 2; pass++) {
        int e = tid + pass * TPB;
        if (e < R2) {
            const float4* src = (const float4*)(g_SpartT + e * PBLK);
            float r0 = 0.f, r1 = 0.f, r2 = 0.f, r3 = 0.f;
            #pragma unroll
            for (int q = 0; q < PBLK / 16; q++) {
                float4 s0 = src[4 * q + 0];
                float4 s1 = src[4 * q + 1];
                float4 s2 = src[4 * q + 2];
                float4 s3 = src[4 * q + 3];
                r0 += (s0.x + s0.y) + (s0.z + s0.w);
                r1 += (s1.x + s1.y) + (s1.z + s1.w);
                r2 += (s2.x + s2.y) + (s2.z + s2.w);
                r3 += (s3.x + s3.y) + (s3.z + s3.w);
            }
            int j = e / RNK, k = e - j * RNK;
            S[j * RPAD + k] = (r0 + r1) + (r2 + r3);
        } else if (e < SPAD) {
            int j = e - R2;        // zero pad column
            S[j * RPAD + (RPAD - 1)] = 0.0f;
        }
    }
    __syncthreads();

    // ---------- bilinear form u0^T S u1 ----------
    const float4* u1v = (const float4*)u1;
    float agg = 0.0f;
    #pragma unroll
    for (int j = 0; j < RNK; j++) {
        const float4* Sv = (const float4*)(S + j * RPAD);
        float t0 = 0.f, t1 = 0.f, t2 = 0.f, t3 = 0.f;
        #pragma unroll
        for (int q = 0; q < RPAD / 4; q++) {
            float4 sv = Sv[q];
            float4 uv = u1v[q];
            t0 = fmaf(sv.x, uv.x, t0);
            t1 = fmaf(sv.y, uv.y, t1);
            t2 = fmaf(sv.z, uv.z, t2);
            t3 = fmaf(sv.w, uv.w, t3);
        }
        agg = fmaf(u0[j], (t0 + t1) + (t2 + t3), agg);
    }

    // ---------- tiny MLP + 2-way softmax ----------
    float hh[4];
    #pragma unroll
    for (int j = 0; j < 4; j++)
        hh[j] = fast_tanh(fmaf(agg, W1[j], b1[j]));

    float l0 = b2[0], l1 = b2[1];
    #pragma unroll
    for (int j = 0; j < 4; j++) {
        l0 = fmaf(W2[j],     hh[j], l0);
        l1 = fmaf(W2[4 + j], hh[j], l1);
    }

    const float LOG2E = 1.4426950408889634f;
    float mx = fmaxf(l0, l1);
    float e0 = ex2_approx((l0 - mx) * LOG2E);
    float e1 = ex2_approx((l1 - mx) * LOG2E);
    float inv = rcp_approx(e0 + e1);
    out[2 * n + 0] = e0 * inv;
    out[2 * n + 1] = e1 * inv;
}

// -------------------------------------------------------------------------
extern "C" void kernel_launch(void* const* d_in, const int* in_sizes, int n_in,
                              void* d_out, int out_size)
{
    const float* x           = (const float*)d_in[0];
    const float* layer_W     = (const float*)d_in[1];
    const float* layer_b     = (const float*)d_in[2];
    const float* layer_scale = (const float*)d_in[3];
    const float* layer_shift = (const float*)d_in[4];
    const float* refset      = (const float*)d_in[5];
    const float* W1          = (const float*)d_in[6];
    const float* b1          = (const float*)d_in[7];
    const float* W2          = (const float*)d_in[8];
    const float* b2          = (const float*)d_in[9];
    float* out = (float*)d_out;

    // Primary: producers (normal launch)
    producer_kernel<<<PBLK, TPB>>>(refset);

    // Secondary: consumers with Programmatic Dependent Launch — may start
    // while the producer grid is still running; cudaGridDependencySynchronize
    // inside gates the dependent reads.
    cudaLaunchConfig_t cfg = {};
    cfg.gridDim  = dim3(NBLK, 1, 1);
    cfg.blockDim = dim3(TPB, 1, 1);
    cfg.dynamicSmemBytes = 0;
    cfg.stream = 0;
    cudaLaunchAttribute attrs[1];
    attrs[0].id = cudaLaunchAttributeProgrammaticStreamSerialization;
    attrs[0].val.programmaticStreamSerializationAllowed = 1;
    cfg.attrs = attrs;
    cfg.numAttrs = 1;

    cudaLaunchKernelEx(&cfg, consumer_kernel,
                       x, layer_W, layer_b, layer_scale, layer_shift,
                       W1, b1, W2, b2, (float*)d_out);
}

// round 9
// speedup vs baseline: 1.1837x; 1.1837x over previous
#include <cuda_runtime.h>

// Problem constants
#define N_PTS   16384
#define M_REF   4096
#define L_LAYERS 8
#define KMAX    6                    // trunc err ~ 2*I_7(2)/sqrt(M) ~ 7e-6 on agg
#define RNK     (2*KMAX + 1)         // 13 features per coordinate
#define RPAD    16                   // padded row (float4-aligned)
#define R2      (RNK*RNK)            // 169
#define SPAD    (RNK*RPAD)           // 208
#define PBLK    64                   // producer blocks (S partials)
#define MPB     (M_REF / PBLK)       // 64 reference points per producer block
#define TPB     256
#define NBLK    (N_PTS / TPB)        // 64 consumer blocks
#define SCALE   4.4711032452e-6f     // exp(-4) / 4096

// Scratch (device global; fully rewritten by producer every call)
__device__ float g_SpartT[R2 * PBLK];   // transposed: [e][p], 256B rows

// c_0 = I_0(2), c_k = 2*I_k(2)
__constant__ float C_BES[KMAX + 1] = {
    2.27958530f, 3.18127371f, 1.37789690f, 0.42547992f,
    0.10145715f, 0.01965093f, 3.2003260e-3f
};

__device__ __forceinline__ float ex2_approx(float d) {
    float r; asm("ex2.approx.ftz.f32 %0, %1;" : "=f"(r) : "f"(d)); return r;
}
__device__ __forceinline__ float rcp_approx(float d) {
    float r; asm("rcp.approx.ftz.f32 %0, %1;" : "=f"(r) : "f"(d)); return r;
}
// tanh via e^{2x}: 1 - 2/(e^{2x}+1). Saturates correctly. Rel err ~1e-6.
__device__ __forceinline__ float fast_tanh(float x) {
    float e = ex2_approx(x * 2.8853900817779268f);
    return fmaf(-2.0f, rcp_approx(e + 1.0f), 1.0f);
}

// Fourier features via MUFU sin/cos + Chebyshev recurrence.
// out[0]=w0; out[k]=w_k cos(k a); out[KMAX+k]=w_k sin(k a), k=1..KMAX.
template <bool WEIGHTED>
__device__ __forceinline__ void four_feats(float ang, float* out, float wscale) {
    float s = __sinf(ang);
    float c = __cosf(ang);
    float c2 = 2.0f * c;
    float ckm = 1.0f, skm = 0.0f;
    float ck  = c,    sk  = s;
    out[0] = WEIGHTED ? C_BES[0] * wscale : 1.0f;
    #pragma unroll
    for (int k = 1; k <= KMAX; k++) {
        float w = WEIGHTED ? C_BES[k] * wscale : 1.0f;
        out[k]        = w * ck;
        out[KMAX + k] = w * sk;
        float cn = fmaf(c2, ck, -ckm);
        float sn = fmaf(c2, sk, -skm);
        ckm = ck; skm = sk; ck = cn; sk = sn;
    }
}

// -------------------------------------------------------------------------
// Kernel 1: 64 producer blocks x 256 threads.
//   threads [0,64): Fourier features of this block's 64 reference points.
//   threads [0,169): one S element each, 64-iteration smem dot product.
// -------------------------------------------------------------------------
__global__ void __launch_bounds__(TPB) prep_kernel(
    const float* __restrict__ refset)
{
    __shared__ __align__(16) float V0[MPB * RNK];
    __shared__ __align__(16) float V1[MPB * RNK];

    const int b   = blockIdx.x;
    const int tid = threadIdx.x;

    if (tid < MPB) {
        int m = b * MPB + tid;
        float2 g = ((const float2*)refset)[m];
        float v0[RNK], v1[RNK];
        four_feats<true>(g.x, v0, SCALE);   // e^-4/M folded into v0
        four_feats<true>(g.y, v1, 1.0f);
        #pragma unroll
        for (int i = 0; i < RNK; i++) {
            V0[tid * RNK + i] = v0[i];
            V1[tid * RNK + i] = v1[i];
        }
    }
    __syncthreads();

    if (tid < R2) {
        int j = tid / RNK, k = tid - (tid / RNK) * RNK;
        float a0 = 0.f, a1 = 0.f, a2 = 0.f, a3 = 0.f;
        #pragma unroll 4
        for (int mm = 0; mm < MPB; mm += 4) {
            a0 = fmaf(V0[(mm + 0) * RNK + j], V1[(mm + 0) * RNK + k], a0);
            a1 = fmaf(V0[(mm + 1) * RNK + j], V1[(mm + 1) * RNK + k], a1);
            a2 = fmaf(V0[(mm + 2) * RNK + j], V1[(mm + 2) * RNK + k], a2);
            a3 = fmaf(V0[(mm + 3) * RNK + j], V1[(mm + 3) * RNK + k], a3);
        }
        g_SpartT[tid * PBLK + b] = (a0 + a1) + (a2 + a3);
    }
}

// -------------------------------------------------------------------------
// Kernel 2: 64 consumer blocks x 256 threads. One n per thread.
//   tanh chain + u-features, one-element-per-thread S reduce (16 x LDG.128),
//   bilinear form, MLP, softmax.
// -------------------------------------------------------------------------
__global__ void __launch_bounds__(TPB) final_kernel(
    const float* __restrict__ x,
    const float* __restrict__ layer_W,
    const float* __restrict__ layer_b,
    const float* __restrict__ layer_scale,
    const float* __restrict__ layer_shift,
    const float* __restrict__ W1,
    const float* __restrict__ b1,
    const float* __restrict__ W2,
    const float* __restrict__ b2,
    float* __restrict__ out)
{
    __shared__ __align__(16) float S[SPAD];   // 13 rows x 16 (pads = 0)

    const int tid = threadIdx.x;
    const int n   = blockIdx.x * TPB + tid;

    // ---- one-element-per-thread S reduce (issue loads first) ----
    if (tid < R2) {
        const float4* src = (const float4*)(g_SpartT + tid * PBLK);
        float r0 = 0.f, r1 = 0.f, r2 = 0.f, r3 = 0.f;
        #pragma unroll
        for (int q = 0; q < PBLK / 16; q++) {
            float4 s0 = src[4 * q + 0];
            float4 s1 = src[4 * q + 1];
            float4 s2 = src[4 * q + 2];
            float4 s3 = src[4 * q + 3];
            r0 += (s0.x + s0.y) + (s0.z + s0.w);
            r1 += (s1.x + s1.y) + (s1.z + s1.w);
            r2 += (s2.x + s2.y) + (s2.z + s2.w);
            r3 += (s3.x + s3.y) + (s3.z + s3.w);
        }
        int j = tid / RNK, k = tid - (tid / RNK) * RNK;
        S[j * RPAD + k] = (r0 + r1) + (r2 + r3);
    } else if (tid < R2 + RNK * (RPAD - RNK)) {
        int idx = tid - R2;                     // 39 pad slots: 13 rows x 3
        int j = idx / (RPAD - RNK);
        int k = RNK + idx - j * (RPAD - RNK);
        S[j * RPAD + k] = 0.0f;
    }

    // ---- per-n tanh chain + u-features (overlaps the LDG latency) ----
    float2 xin = ((const float2*)x)[n];
    float h0 = xin.x, h1 = xin.y;
    #pragma unroll
    for (int l = 0; l < L_LAYERS; l++) {
        float w00 = layer_W[l * 4 + 0], w01 = layer_W[l * 4 + 1];
        float w10 = layer_W[l * 4 + 2], w11 = layer_W[l * 4 + 3];
        float c0  = layer_b[l * 2 + 0],  c1  = layer_b[l * 2 + 1];
        float sc0 = layer_scale[l * 2 + 0], sc1 = layer_scale[l * 2 + 1];
        float t0  = layer_shift[l * 2 + 0], t1  = layer_shift[l * 2 + 1];
        float u0 = fast_tanh(fmaf(h0, w00, fmaf(h1, w01, c0)));
        float u1 = fast_tanh(fmaf(h0, w10, fmaf(h1, w11, c1)));
        h0 = fmaf(u0, sc0, t0);
        h1 = fmaf(u1, sc1, t1);
    }

    float u0[RNK];
    __align__(16) float u1[RPAD];
    four_feats<false>(h0, u0, 1.0f);
    four_feats<false>(h1, u1, 1.0f);
    #pragma unroll
    for (int k = RNK; k < RPAD; k++) u1[k] = 0.0f;

    __syncthreads();

    // ---- bilinear form u0^T S u1 ----
    const float4* u1v = (const float4*)u1;
    float agg = 0.0f;
    #pragma unroll
    for (int j = 0; j < RNK; j++) {
        const float4* Sv = (const float4*)(S + j * RPAD);
        float t0 = 0.f, t1 = 0.f, t2 = 0.f, t3 = 0.f;
        #pragma unroll
        for (int q = 0; q < RPAD / 4; q++) {
            float4 sv = Sv[q];
            float4 uv = u1v[q];
            t0 = fmaf(sv.x, uv.x, t0);
            t1 = fmaf(sv.y, uv.y, t1);
            t2 = fmaf(sv.z, uv.z, t2);
            t3 = fmaf(sv.w, uv.w, t3);
        }
        agg = fmaf(u0[j], (t0 + t1) + (t2 + t3), agg);
    }

    // ---- tiny MLP + 2-way softmax ----
    float hh[4];
    #pragma unroll
    for (int j = 0; j < 4; j++)
        hh[j] = fast_tanh(fmaf(agg, W1[j], b1[j]));

    float l0 = b2[0], l1 = b2[1];
    #pragma unroll
    for (int j = 0; j < 4; j++) {
        l0 = fmaf(W2[j],     hh[j], l0);
        l1 = fmaf(W2[4 + j], hh[j], l1);
    }

    const float LOG2E = 1.4426950408889634f;
    float mx = fmaxf(l0, l1);
    float e0 = ex2_approx((l0 - mx) * LOG2E);
    float e1 = ex2_approx((l1 - mx) * LOG2E);
    float inv = rcp_approx(e0 + e1);
    ((float2*)out)[n] = make_float2(e0 * inv, e1 * inv);
}

// -------------------------------------------------------------------------
extern "C" void kernel_launch(void* const* d_in, const int* in_sizes, int n_in,
                              void* d_out, int out_size)
{
    const float* x           = (const float*)d_in[0];
    const float* layer_W     = (const float*)d_in[1];
    const float* layer_b     = (const float*)d_in[2];
    const float* layer_scale = (const float*)d_in[3];
    const float* layer_shift = (const float*)d_in[4];
    const float* refset      = (const float*)d_in[5];
    const float* W1          = (const float*)d_in[6];
    const float* b1          = (const float*)d_in[7];
    const float* W2          = (const float*)d_in[8];
    const float* b2          = (const float*)d_in[9];
    float* out = (float*)d_out;

    prep_kernel<<<PBLK, TPB>>>(refset);
    final_kernel<<<NBLK, TPB>>>(x, layer_W, layer_b, layer_scale, layer_shift,
                                W1, b1, W2, b2, out);
}